// round 9
// baseline (speedup 1.0000x reference)
#include <cuda_runtime.h>
#include <stdint.h>

// Algebraic feature expansion:
//   out[:, 0:16]    = x
//   out[:, 16:136]  = pair products  x[a]*x[b]   (lex order)
//   out[:, 136:696] = triple products x[a]*x[b]*x[c] (lex order)
// B=262144 rows, 696 out cols. HBM-store-bound (~730 MB out).
//
// v9: byte-for-byte v2 (best known codegen: 40 regs, full 16-row unroll,
// __stcs, pointer-decoded operands) with ONE change: grid = 1184.
// With regs=40, BLK=192 only 8 blocks/SM are resident (65536/7680 = 8.5);
// v2's grid of 1480 ran as 1184 resident + a 296-block straggler wave
// (25% of the machine active for the last ~20% of work). 1184 = exactly
// one persistent wave, 13-14 tiles/block.

#define NC    16
#define NPAIR 120
#define OUTC  696
#define Q4    174          // OUTC / 4
#define RTILE 16           // rows per tile
#define PAD   20           // floats per cached row (16 data + 1.0 dummy + align)
#define BLK   192          // 6 warps; threads [0,174) compute
#define GRID  (148 * 8)    // exactly the resident-block count

__global__ __launch_bounds__(BLK) void algebraic_expand_kernel(
    const float* __restrict__ x,
    float4* __restrict__ out4,
    int nrows)
{
    __shared__ __align__(16) uint32_t stab[OUTC];
    __shared__ __align__(16) float xs[RTILE][PAD];

    const int t = threadIdx.x;

    // ---- Build packed index table once (a | b<<8 | c<<16; 16 = dummy -> 1.0) ----
    for (int col = t; col < OUTC; col += BLK) {
        int a, b, c;
        if (col < NC) {
            a = col; b = 16; c = 16;
        } else if (col < NC + NPAIR) {
            int p = col - NC;
            a = 0;
            for (;; a++) { int cnt = NC - 1 - a; if (p < cnt) break; p -= cnt; }
            b = a + 1 + p;
            c = 16;
        } else {
            int q = col - NC - NPAIR;
            a = 0;
            for (;; a++) {
                int m = NC - 1 - a;
                int cnt = (m * (m - 1)) >> 1;     // C(m,2)
                if (q < cnt) break;
                q -= cnt;
            }
            b = a + 1;
            for (;; b++) { int cnt = NC - 1 - b; if (q < cnt) break; q -= cnt; }
            c = b + 1 + q;
        }
        stab[col] = (uint32_t)a | ((uint32_t)b << 8) | ((uint32_t)c << 16);
    }
    __syncthreads();

    // ---- Decode this thread's fixed chunk ONCE into register pointers ----
    const bool active = (t < Q4);
    const float* base = &xs[0][0];
    const float *p0 = base, *p1 = base, *p2 = base, *p3 = base,
                *p4 = base, *p5 = base, *p6 = base, *p7 = base,
                *p8 = base, *p9 = base, *pa = base, *pb = base;
    if (active) {
        uint4 pk = reinterpret_cast<const uint4*>(stab)[t];
        p0 = base + ( pk.x        & 255u);
        p1 = base + ((pk.x >>  8) & 255u);
        p2 = base + ( pk.x >> 16        );
        p3 = base + ( pk.y        & 255u);
        p4 = base + ((pk.y >>  8) & 255u);
        p5 = base + ( pk.y >> 16        );
        p6 = base + ( pk.z        & 255u);
        p7 = base + ((pk.z >>  8) & 255u);
        p8 = base + ( pk.z >> 16        );
        p9 = base + ( pk.w        & 255u);
        pa = base + ((pk.w >>  8) & 255u);
        pb = base + ( pk.w >> 16        );
    }

    const int ntiles = (nrows + RTILE - 1) / RTILE;

    for (int tile = blockIdx.x; tile < ntiles; tile += gridDim.x) {
        const int row0 = tile * RTILE;

        __syncthreads();   // xs reuse safety

        // ---- Coalesced tile load: RTILE*16 floats = 64 float4 ----
        if (t < RTILE * NC / 4) {
            const int r = t >> 2;
            if (row0 + r < nrows) {
                float4 v = reinterpret_cast<const float4*>(
                               x + (size_t)row0 * NC)[t];
                *reinterpret_cast<float4*>(&xs[r][(t & 3) << 2]) = v;
            }
        }
        if (t < RTILE) xs[t][16] = 1.0f;   // dummy operand
        __syncthreads();

        if (!active) continue;

        float4* ob = out4 + (size_t)row0 * Q4 + t;

        if (row0 + RTILE <= nrows) {
            // fast path: full tile, all offsets compile-time immediates
            #pragma unroll
            for (int r = 0; r < RTILE; r++) {
                const int o = r * PAD;
                float4 v;
                v.x = p0[o] * p1[o] * p2[o];
                v.y = p3[o] * p4[o] * p5[o];
                v.z = p6[o] * p7[o] * p8[o];
                v.w = p9[o] * pa[o] * pb[o];
                __stcs(&ob[(size_t)r * Q4], v);
            }
        } else {
            const int rem = nrows - row0;
            for (int r = 0; r < rem; r++) {
                const int o = r * PAD;
                float4 v;
                v.x = p0[o] * p1[o] * p2[o];
                v.y = p3[o] * p4[o] * p5[o];
                v.z = p6[o] * p7[o] * p8[o];
                v.w = p9[o] * pa[o] * pb[o];
                __stcs(&ob[(size_t)r * Q4], v);
            }
        }
    }
}

extern "C" void kernel_launch(void* const* d_in, const int* in_sizes, int n_in,
                              void* d_out, int out_size)
{
    const float* x = (const float*)d_in[0];
    const int nrows = in_sizes[0] / NC;

    const int ntiles = (nrows + RTILE - 1) / RTILE;
    int grid = GRID;                     // one persistent wave (8 blocks/SM)
    if (grid > ntiles) grid = ntiles;

    algebraic_expand_kernel<<<grid, BLK>>>(x, (float4*)d_out, nrows);
}

// round 10
// speedup vs baseline: 1.1821x; 1.1821x over previous
#include <cuda_runtime.h>
#include <stdint.h>

// Algebraic feature expansion:
//   out[:, 0:16]    = x
//   out[:, 16:136]  = pair products  x[a]*x[b]   (lex order)
//   out[:, 136:696] = triple products x[a]*x[b]*x[c] (lex order)
// B=262144 rows, 696 out cols. HBM-store-bound (~730 MB out).
//
// v10: one tile per block, grid = ntiles (16384). R9 showed more
// oversubscription beats a persistent wave (1480 blocks: 111.3us vs 1184:
// 121.3us, identical code): queued blocks let the CTA scheduler overlap one
// block's serialized load phase with another's store burst. Per-block
// preamble made ~free by moving the index table to compile-time __constant__
// memory (constexpr generator, same combination order as itertools).

#define NC    16
#define NPAIR 120
#define OUTC  696
#define Q4    174          // OUTC / 4
#define RTILE 16           // rows per tile
#define PAD   20           // floats per cached row (16 data + 1.0 dummy + align)
#define BLK   192          // 6 warps; threads [0,174) compute, [0,64) load

// ---- Compile-time packed index table: a | b<<8 | c<<16 (16 = dummy -> 1.0) ----
struct Tab { unsigned v[OUTC]; };

static constexpr Tab make_tab() {
    Tab t{};
    int col = 0;
    for (int a = 0; a < NC; a++)
        t.v[col++] = (unsigned)a | (16u << 8) | (16u << 16);
    for (int a = 0; a < NC; a++)
        for (int b = a + 1; b < NC; b++)
            t.v[col++] = (unsigned)a | ((unsigned)b << 8) | (16u << 16);
    for (int a = 0; a < NC; a++)
        for (int b = a + 1; b < NC; b++)
            for (int c = b + 1; c < NC; c++)
                t.v[col++] = (unsigned)a | ((unsigned)b << 8) | ((unsigned)c << 16);
    return t;
}

__constant__ Tab ctab = make_tab();

__global__ __launch_bounds__(BLK) void algebraic_expand_kernel(
    const float* __restrict__ x,
    float4* __restrict__ out4,
    int nrows)
{
    __shared__ __align__(16) float xs[RTILE][PAD];

    const int t    = threadIdx.x;
    const int row0 = blockIdx.x * RTILE;

    // ---- Kick off the tile load first (LDG in flight during decode) ----
    float4 ld;
    const bool loader = (t < RTILE * NC / 4);     // 64 loader threads
    const int lr = t >> 2;
    const int lc = (t & 3) << 2;
    const bool do_ld = loader && (row0 + lr < nrows);
    if (do_ld)
        ld = reinterpret_cast<const float4*>(x + (size_t)row0 * NC)[t];

    // ---- Decode this thread's fixed chunk from __constant__ (overlaps LDG) ----
    const bool active = (t < Q4);
    const float* base = &xs[0][0];
    const float *p0 = base, *p1 = base, *p2 = base, *p3 = base,
                *p4 = base, *p5 = base, *p6 = base, *p7 = base,
                *p8 = base, *p9 = base, *pa = base, *pb = base;
    if (active) {
        const uint4 pk = reinterpret_cast<const uint4*>(ctab.v)[t];
        p0 = base + ( pk.x        & 255u);
        p1 = base + ((pk.x >>  8) & 255u);
        p2 = base + ( pk.x >> 16        );
        p3 = base + ( pk.y        & 255u);
        p4 = base + ((pk.y >>  8) & 255u);
        p5 = base + ( pk.y >> 16        );
        p6 = base + ( pk.z        & 255u);
        p7 = base + ((pk.z >>  8) & 255u);
        p8 = base + ( pk.z >> 16        );
        p9 = base + ( pk.w        & 255u);
        pa = base + ((pk.w >>  8) & 255u);
        pb = base + ( pk.w >> 16        );
    }

    // ---- Stage the tile ----
    if (do_ld)
        *reinterpret_cast<float4*>(&xs[lr][lc]) = ld;
    if (t < RTILE) xs[t][16] = 1.0f;   // dummy operand
    __syncthreads();

    if (!active) return;

    float4* ob = out4 + (size_t)row0 * Q4 + t;

    if (row0 + RTILE <= nrows) {
        // fast path: full tile, all offsets compile-time immediates
        #pragma unroll
        for (int r = 0; r < RTILE; r++) {
            const int o = r * PAD;
            float4 v;
            v.x = p0[o] * p1[o] * p2[o];
            v.y = p3[o] * p4[o] * p5[o];
            v.z = p6[o] * p7[o] * p8[o];
            v.w = p9[o] * pa[o] * pb[o];
            __stcs(&ob[(size_t)r * Q4], v);
        }
    } else {
        const int rem = nrows - row0;
        for (int r = 0; r < rem; r++) {
            const int o = r * PAD;
            float4 v;
            v.x = p0[o] * p1[o] * p2[o];
            v.y = p3[o] * p4[o] * p5[o];
            v.z = p6[o] * p7[o] * p8[o];
            v.w = p9[o] * pa[o] * pb[o];
            __stcs(&ob[(size_t)r * Q4], v);
        }
    }
}

extern "C" void kernel_launch(void* const* d_in, const int* in_sizes, int n_in,
                              void* d_out, int out_size)
{
    const float* x = (const float*)d_in[0];
    const int nrows = in_sizes[0] / NC;

    const int ntiles = (nrows + RTILE - 1) / RTILE;   // 16384 for B=262144
    algebraic_expand_kernel<<<ntiles, BLK>>>(x, (float4*)d_out, nrows);
}